// round 11
// baseline (speedup 1.0000x reference)
#include <cuda_runtime.h>
#include <math.h>

#define HHN  51
#define NSEQ 16
#define NT   408          // phase1: 102 g-quads x 2 sg x 2 ks ; phase2: 51 x 2 x 4
#define NBLK 128
#define TSZ  2048
#define XCH  64

// shared layout (floats)
#define OFF_W1 0                      // [52][204]  gate-interleaved, k-major
#define OFF_W2 (OFF_W1 + 52*204)      // [104][204] rows 0..51: W_ih2 (h1), 52..103: W_hh2 (h2)
#define OFF_S0 (OFF_W2 + 104*204)     // state [104][16]: rows 0..50 h1, 52..102 h2 (51,103 = 0 pad)
#define OFF_S1 (OFF_S0 + 104*16)
#define OFF_P2 (OFF_S1 + 104*16)      // layer-2 partial [51][4][16]
#define OFF_X  (OFF_P2 + 204*16)      // [64][16] t-major
#define OFF_Y  (OFF_X  + 64*16)       // [64][16]
#define OFF_WL (OFF_Y  + 64*16)       // [52]: 0..50 W_lin, 51 b_lin
#define SMEM_FLOATS (OFF_WL + 52)

typedef unsigned long long u64;

__device__ __forceinline__ u64 pack2(float a, float b) {
    u64 d; asm("mov.b64 %0,{%1,%2};" : "=l"(d) : "f"(a), "f"(b)); return d;
}
__device__ __forceinline__ void unpack2(u64 v, float &a, float &b) {
    asm("mov.b64 {%0,%1},%2;" : "=f"(a), "=f"(b) : "l"(v));
}
__device__ __forceinline__ u64 ffma2(u64 a, u64 b, u64 c) {
    u64 d; asm("fma.rn.f32x2 %0,%1,%2,%3;" : "=l"(d) : "l"(a), "l"(b), "l"(c)); return d;
}
__device__ __forceinline__ u64 add2(u64 a, u64 b) {
    u64 d; asm("add.rn.f32x2 %0,%1,%2;" : "=l"(d) : "l"(a), "l"(b)); return d;
}

__device__ __forceinline__ float fsig(float x) {
    float e = __expf(fminf(-x, 80.f));
    return __fdividef(1.f, 1.f + e);
}
__device__ __forceinline__ float ftanh_f(float x) {
    float ax = fabsf(x);
    float e  = __expf(-2.f * ax);
    float t  = __fdividef(1.f - e, 1.f + e);
    return x >= 0.f ? t : -t;
}

// 4-gate x 4-seqpair matvec tile: acc[q*4+p] = pair (seq 2p, 2p+1) of gate q
__device__ __forceinline__ void mv_tile(const float* __restrict__ wb,
                                        const float* __restrict__ hb,
                                        int k0, int kn, int j, int sgo, u64* acc) {
#pragma unroll 2
    for (int k = k0; k < k0 + kn; k++) {
        const float4 wv = *(const float4*)(wb + k*204 + j);
        const ulonglong2 ha = *(const ulonglong2*)(hb + k*16 + sgo);
        const ulonglong2 hc = *(const ulonglong2*)(hb + k*16 + sgo + 4);
        u64 w0 = pack2(wv.x, wv.x), w1 = pack2(wv.y, wv.y);
        u64 w2 = pack2(wv.z, wv.z), w3 = pack2(wv.w, wv.w);
        acc[0]  = ffma2(w0, ha.x, acc[0]);  acc[1]  = ffma2(w0, ha.y, acc[1]);
        acc[2]  = ffma2(w0, hc.x, acc[2]);  acc[3]  = ffma2(w0, hc.y, acc[3]);
        acc[4]  = ffma2(w1, ha.x, acc[4]);  acc[5]  = ffma2(w1, ha.y, acc[5]);
        acc[6]  = ffma2(w1, hc.x, acc[6]);  acc[7]  = ffma2(w1, hc.y, acc[7]);
        acc[8]  = ffma2(w2, ha.x, acc[8]);  acc[9]  = ffma2(w2, ha.y, acc[9]);
        acc[10] = ffma2(w2, hc.x, acc[10]); acc[11] = ffma2(w2, hc.y, acc[11]);
        acc[12] = ffma2(w3, ha.x, acc[12]); acc[13] = ffma2(w3, ha.y, acc[13]);
        acc[14] = ffma2(w3, hc.x, acc[14]); acc[15] = ffma2(w3, hc.y, acc[15]);
    }
}

__global__ __launch_bounds__(NT, 1)
void lstm2_kernel(const float* __restrict__ in,
                  const float* __restrict__ W_ih1,
                  const float* __restrict__ W_hh1,
                  const float* __restrict__ b_ih1,
                  const float* __restrict__ b_hh1,
                  const float* __restrict__ W_ih2,
                  const float* __restrict__ W_hh2,
                  const float* __restrict__ b_ih2,
                  const float* __restrict__ b_hh2,
                  const float* __restrict__ W_lin,
                  const float* __restrict__ b_lin,
                  float* __restrict__ out)
{
    extern __shared__ float sm[];
    float* sW1 = sm + OFF_W1;
    float* sW2 = sm + OFF_W2;
    float* sP2 = sm + OFF_P2;
    float* sX  = sm + OFF_X;
    float* sY  = sm + OFF_Y;
    float* sWl = sm + OFF_WL;

    const int tid  = threadIdx.x;
    const int seq0 = blockIdx.x * NSEQ;

    // ---- one-time: permuted weights (gate-interleaved, k-major) ----
    for (int i = tid; i < 52*204; i += NT) {
        int k = i / 204, j = i % 204, hh = j >> 2, q = j & 3;
        sW1[i] = (k < HHN) ? W_hh1[(q*HHN + hh)*HHN + k] : 0.f;
    }
    for (int i = tid; i < 104*204; i += NT) {
        int k = i / 204, j = i % 204, hh = j >> 2, q = j & 3;
        float v = 0.f;
        if (k < HHN)                     v = W_ih2[(q*HHN + hh)*HHN + k];
        else if (k >= 52 && k < 52+HHN)  v = W_hh2[(q*HHN + hh)*HHN + (k - 52)];
        sW2[i] = v;
    }
    for (int i = tid; i < 2*104*16; i += NT) sm[OFF_S0 + i] = 0.f;   // both state bufs
    for (int i = tid; i < 52; i += NT)
        sWl[i] = (i < HHN) ? W_lin[i] : b_lin[0];

    // ---- phase-1 thread decode: tid = g*4 + sg*2 + ks ----
    const int ks  = tid & 1;
    const int sg  = (tid >> 1) & 1;
    const int g   = tid >> 2;          // 0..101
    const int u1  = (g >= HHN);        // unit: 0=layer1, 1=layer2 h2-partial
    const int gg  = u1 ? g - HHN : g;  // hidden unit 0..50
    // ---- phase-2 decode: tid = gg2*8 + sg2*4 + ks2 ----
    const int ks2 = tid & 3;
    const int sg2 = (tid >> 2) & 1;
    const int gg2 = tid >> 3;          // 0..50

    const unsigned mask = (tid >= 384) ? 0x00FFFFFFu : 0xFFFFFFFFu;

    // per-thread constant registers
    u64 bd[4], xwd[4];
    {
#pragma unroll
        for (int q = 0; q < 4; q++) {
            float b = u1 ? (b_ih2[q*HHN + gg] + b_hh2[q*HHN + gg])
                         : (b_ih1[q*HHN + gg] + b_hh1[q*HHN + gg]);
            bd[q] = pack2(b, b);
            float w = u1 ? 0.f : W_ih1[q*HHN + gg];
            xwd[q] = pack2(w, w);
        }
    }

    float c1[4] = {0.f, 0.f, 0.f, 0.f};   // unit-0 threads: 4 seqs of layer-1 cell state
    float c2[2] = {0.f, 0.f};             // all threads: 2 seqs of layer-2 cell state

    float* sR  = sm + OFF_S0;
    float* sWb = sm + OFF_S1;

    const int jj  = gg * 4;
    const int sgo = sg * 8;
    const int jj2 = gg2 * 4;
    const int sgo2 = sg2 * 8;

    for (int t = 0; t < TSZ; t++) {
        const int tin = t & (XCH - 1);
        if (tin == 0) {
            if (t == 0) {
                __syncthreads();                 // smem init visible
            } else {
                // finish y(t-1), then flush chunk
                if (tid < 64) {
                    int s = tid >> 2, r = tid & 3;
                    float acc = 0.f;
#pragma unroll
                    for (int k = r; k < HHN; k += 4)
                        acc += sR[(52 + k)*16 + s] * sWl[k];
                    acc += __shfl_xor_sync(0xffffffffu, acc, 1);
                    acc += __shfl_xor_sync(0xffffffffu, acc, 2);
                    if (r == 0) sY[63*16 + s] = acc + sWl[HHN];
                }
                __syncthreads();
                const int tp = t - XCH;
                for (int i = tid; i < NSEQ*XCH; i += NT) {
                    int s = i >> 6, j = i & 63;
                    out[(size_t)(seq0 + s) * TSZ + tp + j] = sY[j*16 + s];
                }
            }
            for (int i = tid; i < NSEQ*XCH; i += NT) {
                int s = i >> 6, j = i & 63;
                sX[j*16 + s] = in[(size_t)(seq0 + s) * TSZ + t + j];
            }
            __syncthreads();
        } else {
            // overlapped y(t-1)
            if (tid < 64) {
                int s = tid >> 2, r = tid & 3;
                float acc = 0.f;
#pragma unroll
                for (int k = r; k < HHN; k += 4)
                    acc += sR[(52 + k)*16 + s] * sWl[k];
                acc += __shfl_xor_sync(0xffffffffu, acc, 1);
                acc += __shfl_xor_sync(0xffffffffu, acc, 2);
                if (r == 0) sY[(tin - 1)*16 + s] = acc + sWl[HHN];
            }
        }

        // ================= PHASE 1: layer-1 gates  ||  layer-2 h2-partial ===========
        {
            u64 acc[16];
            if (ks == 0) {
                if (!u1) {
#pragma unroll
                    for (int p = 0; p < 4; p++) {
                        float2 xp = *(const float2*)(sX + tin*16 + sgo + 2*p);
                        u64 xx = pack2(xp.x, xp.y);
#pragma unroll
                        for (int q = 0; q < 4; q++)
                            acc[q*4 + p] = ffma2(xwd[q], xx, bd[q]);
                    }
                } else {
#pragma unroll
                    for (int q = 0; q < 4; q++)
#pragma unroll
                        for (int p = 0; p < 4; p++)
                            acc[q*4 + p] = bd[q];
                }
            } else {
#pragma unroll
                for (int i = 0; i < 16; i++) acc[i] = 0ull;
            }

            const float* wb = u1 ? (sW2 + 52*204) : sW1;
            const float* hb = u1 ? (sR + 52*16)   : sR;
            mv_tile(wb, hb, ks*26, 26, jj, sgo, acc);

            // butterfly over ks: both lanes get full sums
#pragma unroll
            for (int i = 0; i < 16; i++)
                acc[i] = add2(acc[i], __shfl_xor_sync(mask, acc[i], 1));

            if (!u1) {
                // layer-1 activation: this lane handles seq-pairs p = ks*2, ks*2+1
#pragma unroll
                for (int i = 0; i < 2; i++) {
                    int p = ks*2 + i;
                    float i0,i1,f0,f1,g0,g1,o0,o1;
                    unpack2(acc[0*4 + p], i0, i1);
                    unpack2(acc[1*4 + p], f0, f1);
                    unpack2(acc[2*4 + p], g0, g1);
                    unpack2(acc[3*4 + p], o0, o1);
                    float cA = fsig(f0)*c1[i*2]   + fsig(i0)*ftanh_f(g0);
                    float cB = fsig(f1)*c1[i*2+1] + fsig(i1)*ftanh_f(g1);
                    c1[i*2] = cA; c1[i*2+1] = cB;
                    float hA = fsig(o0)*ftanh_f(cA);
                    float hB = fsig(o1)*ftanh_f(cB);
                    *(float2*)(sWb + gg*16 + sgo + 2*p) = make_float2(hA, hB);
                }
            } else {
                // write layer-2 partial (this lane's seq-pairs)
#pragma unroll
                for (int q = 0; q < 4; q++)
#pragma unroll
                    for (int i = 0; i < 2; i++) {
                        int p = ks*2 + i;
                        *(u64*)(sP2 + (gg*4 + q)*16 + sgo + 2*p) = acc[q*4 + p];
                    }
            }
        }
        __syncthreads();   // h1(t) + partials visible

        // ================= PHASE 2: layer-2 h1-half + finish ========================
        {
            u64 acc[16];
#pragma unroll
            for (int i = 0; i < 16; i++) acc[i] = 0ull;
            mv_tile(sW2, sWb, ks2*13, 13, jj2, sgo2, acc);

            // butterfly over 4 k-slices
#pragma unroll
            for (int i = 0; i < 16; i++)
                acc[i] = add2(acc[i], __shfl_xor_sync(mask, acc[i], 1));
#pragma unroll
            for (int i = 0; i < 16; i++)
                acc[i] = add2(acc[i], __shfl_xor_sync(mask, acc[i], 2));

            // this lane finishes seq-pair p = ks2
            const int p = ks2;
            u64 gi = add2(acc[0*4 + p], *(const u64*)(sP2 + (gg2*4 + 0)*16 + sgo2 + 2*p));
            u64 gf = add2(acc[1*4 + p], *(const u64*)(sP2 + (gg2*4 + 1)*16 + sgo2 + 2*p));
            u64 gz = add2(acc[2*4 + p], *(const u64*)(sP2 + (gg2*4 + 2)*16 + sgo2 + 2*p));
            u64 go = add2(acc[3*4 + p], *(const u64*)(sP2 + (gg2*4 + 3)*16 + sgo2 + 2*p));
            float i0,i1,f0,f1,g0,g1,o0,o1;
            unpack2(gi, i0, i1); unpack2(gf, f0, f1);
            unpack2(gz, g0, g1); unpack2(go, o0, o1);
            float cA = fsig(f0)*c2[0] + fsig(i0)*ftanh_f(g0);
            float cB = fsig(f1)*c2[1] + fsig(i1)*ftanh_f(g1);
            c2[0] = cA; c2[1] = cB;
            float hA = fsig(o0)*ftanh_f(cA);
            float hB = fsig(o1)*ftanh_f(cB);
            *(float2*)(sWb + (52 + gg2)*16 + sgo2 + 2*p) = make_float2(hA, hB);
        }
        __syncthreads();   // h2(t) visible

        { float* tp_ = sR; sR = sWb; sWb = tp_; }
    }

    // final y(2047) + last chunk flush
    if (tid < 64) {
        int s = tid >> 2, r = tid & 3;
        float acc = 0.f;
#pragma unroll
        for (int k = r; k < HHN; k += 4)
            acc += sR[(52 + k)*16 + s] * sWl[k];
        acc += __shfl_xor_sync(0xffffffffu, acc, 1);
        acc += __shfl_xor_sync(0xffffffffu, acc, 2);
        if (r == 0) sY[63*16 + s] = acc + sWl[HHN];
    }
    __syncthreads();
    {
        const int tp = TSZ - XCH;
        for (int i = tid; i < NSEQ*XCH; i += NT) {
            int s = i >> 6, j = i & 63;
            out[(size_t)(seq0 + s) * TSZ + tp + j] = sY[j*16 + s];
        }
    }
}

extern "C" void kernel_launch(void* const* d_in, const int* in_sizes, int n_in,
                              void* d_out, int out_size) {
    (void)in_sizes; (void)n_in; (void)out_size;
    const float* in    = (const float*)d_in[0];
    const float* W_ih1 = (const float*)d_in[1];
    const float* W_hh1 = (const float*)d_in[2];
    const float* b_ih1 = (const float*)d_in[3];
    const float* b_hh1 = (const float*)d_in[4];
    const float* W_ih2 = (const float*)d_in[5];
    const float* W_hh2 = (const float*)d_in[6];
    const float* b_ih2 = (const float*)d_in[7];
    const float* b_hh2 = (const float*)d_in[8];
    const float* W_lin = (const float*)d_in[9];
    const float* b_lin = (const float*)d_in[10];
    float* out = (float*)d_out;

    const size_t smem = (size_t)SMEM_FLOATS * sizeof(float);   // ~162 KB
    cudaFuncSetAttribute(lstm2_kernel,
                         cudaFuncAttributeMaxDynamicSharedMemorySize, (int)smem);
    lstm2_kernel<<<NBLK, NT, smem>>>(in, W_ih1, W_hh1, b_ih1, b_hh1,
                                     W_ih2, W_hh2, b_ih2, b_hh2,
                                     W_lin, b_lin, out);
}

// round 12
// speedup vs baseline: 1.4101x; 1.4101x over previous
#include <cuda_runtime.h>
#include <math.h>

#define HHN  51
#define NU   52        // padded units
#define GW   208       // weight row stride (floats) = NU*4 gates interleaved
#define SST  20        // state row stride (floats)
#define XST  65        // x/y staging row stride
#define NT   416       // 52 units x 8 seq-pairs = 13 warps
#define NBLK 128
#define NSEQ 16
#define TSZ  2048
#define XCH  64

// shared layout (floats)
#define OFF_W1 0                       // [52][208]  layer-1 W_hh, gate-interleaved k-major
#define OFF_W2 (OFF_W1 + 52*GW)        // [104][208] rows 0..50: W_ih2 (vs h1), 52..102: W_hh2
#define OFF_S0 (OFF_W2 + 104*GW)      // state buf0 [104][20]: rows u = h1, 52+u = h2
#define OFF_S1 (OFF_S0 + 104*SST)
#define OFF_X  (OFF_S1 + 104*SST)     // [16][65]
#define OFF_Y  (OFF_X  + NSEQ*XST)    // [16][65]
#define OFF_WL (OFF_Y  + NSEQ*XST)    // [52]: 0..50 W_lin, 51 b_lin
#define SMEM_FLOATS (OFF_WL + 52)

__device__ __forceinline__ float fsig(float x) {
    float e = __expf(fminf(-x, 80.f));
    return __fdividef(1.f, 1.f + e);
}
__device__ __forceinline__ float ftanh_f(float x) {
    float ax = fabsf(x);
    float e  = __expf(-2.f * ax);
    float t  = __fdividef(1.f - e, 1.f + e);
    return x >= 0.f ? t : -t;
}
__device__ __forceinline__ float cellact(float gi, float gf, float gg, float go, float &c) {
    float cn = fsig(gf) * c + fsig(gi) * ftanh_f(gg);
    c = cn;
    return fsig(go) * ftanh_f(cn);
}

// 4-gate x 2-seq matvec: a[q][j] += W[k][4m+q] * h[k][2sg+j]
__device__ __forceinline__ void mv(const float* __restrict__ w,
                                   const float* __restrict__ hb,
                                   int m4, int sg2, int k0, int kn,
                                   float a[4][2]) {
#pragma unroll 4
    for (int k = k0; k < k0 + kn; k++) {
        const float4 wv = *(const float4*)(w  + k*GW  + m4);
        const float2 hv = *(const float2*)(hb + k*SST + sg2);
        a[0][0] += wv.x * hv.x;  a[0][1] += wv.x * hv.y;
        a[1][0] += wv.y * hv.x;  a[1][1] += wv.y * hv.y;
        a[2][0] += wv.z * hv.x;  a[2][1] += wv.z * hv.y;
        a[3][0] += wv.w * hv.x;  a[3][1] += wv.w * hv.y;
    }
}

__global__ __launch_bounds__(NT, 1)
void lstm2_kernel(const float* __restrict__ in,
                  const float* __restrict__ W_ih1,
                  const float* __restrict__ W_hh1,
                  const float* __restrict__ b_ih1,
                  const float* __restrict__ b_hh1,
                  const float* __restrict__ W_ih2,
                  const float* __restrict__ W_hh2,
                  const float* __restrict__ b_ih2,
                  const float* __restrict__ b_hh2,
                  const float* __restrict__ W_lin,
                  const float* __restrict__ b_lin,
                  float* __restrict__ out)
{
    extern __shared__ float sm[];
    float* sW1 = sm + OFF_W1;
    float* sW2 = sm + OFF_W2;
    float* sX  = sm + OFF_X;
    float* sY  = sm + OFF_Y;
    float* sWl = sm + OFF_WL;

    const int tid  = threadIdx.x;
    const int seq0 = blockIdx.x * NSEQ;

    // ---- one-time: gate-interleaved k-major weights ----
    for (int i = tid; i < 52*GW; i += NT) {
        int k = i / GW, j = i % GW, u = j >> 2, q = j & 3;
        sW1[i] = (k < HHN && u < HHN) ? W_hh1[(q*HHN + u)*HHN + k] : 0.f;
    }
    for (int i = tid; i < 104*GW; i += NT) {
        int k = i / GW, j = i % GW, u = j >> 2, q = j & 3;
        float v = 0.f;
        if (u < HHN) {
            if (k < HHN)                     v = W_ih2[(q*HHN + u)*HHN + k];
            else if (k >= 52 && k < 52+HHN)  v = W_hh2[(q*HHN + u)*HHN + (k - 52)];
        }
        sW2[i] = v;
    }
    for (int i = tid; i < 2*104*SST; i += NT) sm[OFF_S0 + i] = 0.f;
    for (int i = tid; i < 52; i += NT)
        sWl[i] = (i < HHN) ? W_lin[i] : b_lin[0];

    // ---- per-thread tile: unit m, seqs {2sg, 2sg+1} ----
    const int m   = tid >> 3;       // 0..51 (51 = inert pad)
    const int sg  = tid & 7;
    const int m4  = m * 4;
    const int sg2 = sg * 2;

    float wi[4], bb1[4], bb2[4];
    {
        const bool ok = (m < HHN);
#pragma unroll
        for (int q = 0; q < 4; q++) {
            wi[q]  = ok ? W_ih1[q*HHN + m] : 0.f;
            bb1[q] = ok ? (b_ih1[q*HHN + m] + b_hh1[q*HHN + m]) : 0.f;
            bb2[q] = ok ? (b_ih2[q*HHN + m] + b_hh2[q*HHN + m]) : 0.f;
        }
    }

    float c1[2] = {0.f, 0.f};
    float c2[2] = {0.f, 0.f};

    float* sR  = sm + OFF_S0;   // state(t-1)
    float* sWb = sm + OFF_S1;   // state(t)

    for (int t = 0; t < TSZ; t++) {
        const int tin = t & (XCH - 1);
        if (tin == 0) {
            if (t == 0) {
                __syncthreads();            // smem init visible
            } else {
                // y(t-1) -> slot 63 of previous chunk
                if (tid < 64) {
                    int s = tid >> 2, r = tid & 3;
                    float acc = 0.f;
#pragma unroll
                    for (int k = r; k < HHN; k += 4)
                        acc += sR[(52 + k)*SST + s] * sWl[k];
                    acc += __shfl_xor_sync(0xffffffffu, acc, 1);
                    acc += __shfl_xor_sync(0xffffffffu, acc, 2);
                    if (r == 0) sY[s*XST + 63] = acc + sWl[HHN];
                }
                __syncthreads();
                const int tp = t - XCH;
                for (int i = tid; i < NSEQ*XCH; i += NT) {
                    int s = i >> 6, j = i & 63;
                    out[(size_t)(seq0 + s) * TSZ + tp + j] = sY[s*XST + j];
                }
            }
            for (int i = tid; i < NSEQ*XCH; i += NT) {
                int s = i >> 6, j = i & 63;
                sX[s*XST + j] = in[(size_t)(seq0 + s) * TSZ + t + j];
            }
            __syncthreads();
        } else {
            // overlapped y(t-1) -> slot tin-1 (reads sR h2 rows; safe until phase C)
            if (tid < 64) {
                int s = tid >> 2, r = tid & 3;
                float acc = 0.f;
#pragma unroll
                for (int k = r; k < HHN; k += 4)
                    acc += sR[(52 + k)*SST + s] * sWl[k];
                acc += __shfl_xor_sync(0xffffffffu, acc, 1);
                acc += __shfl_xor_sync(0xffffffffu, acc, 2);
                if (r == 0) sY[s*XST + (tin - 1)] = acc + sWl[HHN];
            }
        }

        // ===== Layer 1: matvec + activation fused (register-local gates) =====
        {
            float x0 = sX[(sg2    )*XST + tin];
            float x1 = sX[(sg2 + 1)*XST + tin];
            float a[4][2];
#pragma unroll
            for (int q = 0; q < 4; q++) {
                a[q][0] = bb1[q] + wi[q]*x0;
                a[q][1] = bb1[q] + wi[q]*x1;
            }
            mv(sW1, sR, m4, sg2, 0, 52, a);
            float h0 = cellact(a[0][0], a[1][0], a[2][0], a[3][0], c1[0]);
            float h1 = cellact(a[0][1], a[1][1], a[2][1], a[3][1], c1[1]);
            *(float2*)(sWb + m*SST + sg2) = make_float2(h0, h1);
        }
        __syncthreads();   // h1(t) visible; y(t-1) done before h2 rows get rewritten

        // ===== Layer 2: K=104 over [h1(t) | h2(t-1)] =====
        {
            float a[4][2];
#pragma unroll
            for (int q = 0; q < 4; q++) { a[q][0] = bb2[q]; a[q][1] = bb2[q]; }
            mv(sW2, sWb, m4, sg2, 0,  52, a);   // h1(t)
            mv(sW2, sR,  m4, sg2, 52, 52, a);   // h2(t-1)
            float h0 = cellact(a[0][0], a[1][0], a[2][0], a[3][0], c2[0]);
            float h1 = cellact(a[0][1], a[1][1], a[2][1], a[3][1], c2[1]);
            *(float2*)(sWb + (52 + m)*SST + sg2) = make_float2(h0, h1);
        }
        __syncthreads();   // h2(t) visible

        { float* tp_ = sR; sR = sWb; sWb = tp_; }
    }

    // final y(2047) + last chunk flush
    if (tid < 64) {
        int s = tid >> 2, r = tid & 3;
        float acc = 0.f;
#pragma unroll
        for (int k = r; k < HHN; k += 4)
            acc += sR[(52 + k)*SST + s] * sWl[k];
        acc += __shfl_xor_sync(0xffffffffu, acc, 1);
        acc += __shfl_xor_sync(0xffffffffu, acc, 2);
        if (r == 0) sY[s*XST + 63] = acc + sWl[HHN];
    }
    __syncthreads();
    {
        const int tp = TSZ - XCH;
        for (int i = tid; i < NSEQ*XCH; i += NT) {
            int s = i >> 6, j = i & 63;
            out[(size_t)(seq0 + s) * TSZ + tp + j] = sY[s*XST + j];
        }
    }
}

extern "C" void kernel_launch(void* const* d_in, const int* in_sizes, int n_in,
                              void* d_out, int out_size) {
    (void)in_sizes; (void)n_in; (void)out_size;
    const float* in    = (const float*)d_in[0];
    const float* W_ih1 = (const float*)d_in[1];
    const float* W_hh1 = (const float*)d_in[2];
    const float* b_ih1 = (const float*)d_in[3];
    const float* b_hh1 = (const float*)d_in[4];
    const float* W_ih2 = (const float*)d_in[5];
    const float* W_hh2 = (const float*)d_in[6];
    const float* b_ih2 = (const float*)d_in[7];
    const float* b_hh2 = (const float*)d_in[8];
    const float* W_lin = (const float*)d_in[9];
    const float* b_lin = (const float*)d_in[10];
    float* out = (float*)d_out;

    const size_t smem = (size_t)SMEM_FLOATS * sizeof(float);   // ~155 KB
    cudaFuncSetAttribute(lstm2_kernel,
                         cudaFuncAttributeMaxDynamicSharedMemorySize, (int)smem);
    lstm2_kernel<<<NBLK, NT, smem>>>(in, W_ih1, W_hh1, b_ih1, b_hh1,
                                     W_ih2, W_hh2, b_ih2, b_hh2,
                                     W_lin, b_lin, out);
}